// round 8
// baseline (speedup 1.0000x reference)
#include <cuda_runtime.h>

#define NN 50000
#define NE 800000
#define C  128
#define NG 128
#define OC 16
#define NBLK 196   // ceil(50000/256)

// Scratch (static device globals — no allocation in kernel_launch)
__device__ __align__(16) float g_A[NN * C];     // hs = (X@W)*dis  (layer output pre-agg)
__device__ __align__(16) float g_X2[NN * C];    // layer-2 input
__device__ __align__(16) float g_pool[NG * C];
__device__ float g_dis[NN];
__device__ int   g_src[NE];
__device__ int   g_dst[NE];
__device__ int   g_bat[NN];
__device__ int   g_cnt_i[NN];    // in-degree histogram (by dst)
__device__ int   g_cursor[NN];   // fill cursors
__device__ int   g_rs[NN + 1];   // CSR row starts
__device__ int   g_col[NE];      // CSR column (src) ids
__device__ int   g_gcnt[NG];     // nodes per graph
__device__ int   g_bsum[NBLK];   // per-block degree sums
__device__ int   g_boff[NBLK];   // per-block scan offsets
__device__ int   g_done;         // scanA completion counter
__device__ int   g_is64;

// launch 0: zero counters + dtype detect (thread 0)
__global__ void k_init(const int* __restrict__ ei_raw) {
    int i = blockIdx.x * blockDim.x + threadIdx.x;
    if (i == 0) {
        int hi_or = 0, lo_ok = 1;
        for (int j = 0; j < 256; j++) {
            hi_or |= ei_raw[2 * j + 1];
            int lo = ei_raw[2 * j];
            lo_ok &= (lo >= 0 && lo < NN) ? 1 : 0;
        }
        g_is64 = (hi_or == 0 && lo_ok) ? 1 : 0;
        g_done = 0;
    }
    if (i < NN) g_cnt_i[i] = 0;
    if (i < NG * C) g_pool[i] = 0.0f;
    if (i < NG) g_gcnt[i] = 0;
}

// launch 1: dtype-normalize + in-degree histogram + per-graph node counts
// 2 edges per thread, vectorized 16B loads on the int64 path.
__global__ void k_convert_hist(const void* __restrict__ ei_raw, const void* __restrict__ bat_raw) {
    int i = blockIdx.x * blockDim.x + threadIdx.x;   // over NE/2 pairs
    const bool is64 = (g_is64 != 0);
    int e = i * 2;
    if (e < NE) {
        int s0, d0, s1, d1;
        if (is64) {
            const longlong2* ps = (const longlong2*)((const long long*)ei_raw + e);
            const longlong2* pd = (const longlong2*)((const long long*)ei_raw + NE + e);
            longlong2 sv = *ps, dv = *pd;
            s0 = (int)sv.x; s1 = (int)sv.y;
            d0 = (int)dv.x; d1 = (int)dv.y;
        } else {
            const int2* ps = (const int2*)((const int*)ei_raw + e);
            const int2* pd = (const int2*)((const int*)ei_raw + NE + e);
            int2 sv = *ps, dv = *pd;
            s0 = sv.x; s1 = sv.y;
            d0 = dv.x; d1 = dv.y;
        }
        *(int2*)(g_src + e) = make_int2(s0, s1);
        *(int2*)(g_dst + e) = make_int2(d0, d1);
        atomicAdd(&g_cnt_i[d0], 1);
        atomicAdd(&g_cnt_i[d1], 1);
    }
    if (i < NN) {
        int b = is64 ? (int)((const long long*)bat_raw)[i] : ((const int*)bat_raw)[i];
        g_bat[i] = b;
        atomicAdd(&g_gcnt[b], 1);
    }
}

// launch 2: dis = rsqrt(deg+1), per-block sums, last-done block scans block sums
__global__ void k_scanA() {
    int t = threadIdx.x;
    int i = blockIdx.x * blockDim.x + t;
    int c = (i < NN) ? g_cnt_i[i] : 0;
    if (i < NN) g_dis[i] = rsqrtf((float)(c + 1));

    // block reduce
    int r = c;
#pragma unroll
    for (int off = 16; off > 0; off >>= 1)
        r += __shfl_down_sync(0xffffffffu, r, off);
    __shared__ int ws[8];
    int lane = t & 31, w = t >> 5;
    if (lane == 0) ws[w] = r;
    __syncthreads();
    __shared__ int isLast;
    if (t == 0) {
        int s = 0;
#pragma unroll
        for (int j = 0; j < 8; j++) s += ws[j];
        g_bsum[blockIdx.x] = s;
        __threadfence();
        int v = atomicAdd(&g_done, 1);
        isLast = (v == gridDim.x - 1) ? 1 : 0;
    }
    __syncthreads();
    if (isLast) {
        // exclusive scan of NBLK block sums (Hillis-Steele over 256)
        __shared__ int s[256];
        int v = (t < NBLK) ? g_bsum[t] : 0;
        s[t] = v;
        __syncthreads();
#pragma unroll
        for (int off = 1; off < 256; off <<= 1) {
            int x = (t >= off) ? s[t - off] : 0;
            __syncthreads();
            s[t] += x;
            __syncthreads();
        }
        if (t < NBLK) g_boff[t] = s[t] - v;
    }
}

// launches 3,7: out = (X @ W) * dis[row].  BM=64 rows/block, 256 threads.
// Inner loop uses packed fma.rn.f32x2.
__global__ __launch_bounds__(256) void k_gemm(
        const float* __restrict__ X, const float* __restrict__ W,
        const float* __restrict__ dis, float* __restrict__ out) {
    extern __shared__ float sm[];
    float4* Ws4 = (float4*)sm;             // 128 x 32 float4 (64KB)
    float4* Xs4 = (float4*)(sm + C * C);   // 64 x 32 float4  (32KB)
    const unsigned long long* Ws8 = (const unsigned long long*)sm;
    const int tid = threadIdx.x;
    const int bm = blockIdx.x * 64;

#pragma unroll
    for (int t = 0; t < 16; t++) {
        int idx = tid + t * 256;
        Ws4[idx] = ((const float4*)W)[idx];
    }
#pragma unroll
    for (int t = 0; t < 8; t++) {
        int idx = tid + t * 256;
        int row = idx >> 5, c4 = idx & 31;
        int gr = bm + row;
        float4 v = make_float4(0.f, 0.f, 0.f, 0.f);
        if (gr < NN) v = ((const float4*)X)[gr * 32 + c4];
        Xs4[idx] = v;
    }
    __syncthreads();

    const int tx = tid & 31;
    const int ty = tid >> 5;

    unsigned long long acc2[8][2];
#pragma unroll
    for (int i = 0; i < 8; i++) { acc2[i][0] = 0ULL; acc2[i][1] = 0ULL; }

#pragma unroll 2
    for (int k4 = 0; k4 < 32; k4++) {
        float4 a4[8];
#pragma unroll
        for (int i = 0; i < 8; i++) a4[i] = Xs4[(ty * 8 + i) * 32 + k4];  // warp-broadcast
#pragma unroll
        for (int kk = 0; kk < 4; kk++) {
            int base = ((k4 * 4 + kk) * 32 + tx) * 2;
            unsigned long long bxy = Ws8[base];
            unsigned long long bzw = Ws8[base + 1];
#pragma unroll
            for (int i = 0; i < 8; i++) {
                float av = (kk == 0) ? a4[i].x : (kk == 1) ? a4[i].y : (kk == 2) ? a4[i].z : a4[i].w;
                unsigned int ab = __float_as_uint(av);
                unsigned long long av2;
                asm("mov.b64 %0, {%1, %1};" : "=l"(av2) : "r"(ab));
                asm("fma.rn.f32x2 %0, %1, %2, %0;" : "+l"(acc2[i][0]) : "l"(av2), "l"(bxy));
                asm("fma.rn.f32x2 %0, %1, %2, %0;" : "+l"(acc2[i][1]) : "l"(av2), "l"(bzw));
            }
        }
    }

#pragma unroll
    for (int i = 0; i < 8; i++) {
        int r = bm + ty * 8 + i;
        if (r < NN) {
            float s = dis[r];
            unsigned int x0, x1, x2, x3;
            asm("mov.b64 {%0, %1}, %2;" : "=r"(x0), "=r"(x1) : "l"(acc2[i][0]));
            asm("mov.b64 {%0, %1}, %2;" : "=r"(x2), "=r"(x3) : "l"(acc2[i][1]));
            ((float4*)(out + r * C))[tx] = make_float4(
                __uint_as_float(x0) * s, __uint_as_float(x1) * s,
                __uint_as_float(x2) * s, __uint_as_float(x3) * s);
        }
    }
}

// launch 4: per-element exclusive scan + write rs/cursor
__global__ void k_scanB() {
    int t = threadIdx.x;
    int i = blockIdx.x * blockDim.x + t;
    int c = (i < NN) ? g_cnt_i[i] : 0;
    int lane = t & 31, w = t >> 5;
    int incl = c;
#pragma unroll
    for (int off = 1; off < 32; off <<= 1) {
        int n = __shfl_up_sync(0xffffffffu, incl, off);
        if (lane >= off) incl += n;
    }
    __shared__ int wsum[8], woff[8];
    if (lane == 31) wsum[w] = incl;
    __syncthreads();
    if (t == 0) {
        int run = 0;
#pragma unroll
        for (int j = 0; j < 8; j++) { woff[j] = run; run += wsum[j]; }
    }
    __syncthreads();
    if (i < NN) {
        int pre = (incl - c) + woff[w] + g_boff[blockIdx.x];
        g_rs[i] = pre;
        g_cursor[i] = pre;
    }
    if (i == 0) g_rs[NN] = NE;
}

// launch 5: CSR fill
__global__ void k_fill() {
    int e = blockIdx.x * blockDim.x + threadIdx.x;
    if (e < NE) {
        int d = g_dst[e];
        int off = atomicAdd(&g_cursor[d], 1);
        g_col[off] = g_src[e];
    }
}

// gather core: acc = hs[d] (self loop) + sum_{e in row d} hs[col[e]], 8-way unrolled
__device__ __forceinline__ float4 agg_row(const float4* __restrict__ hs4, int d, int lane) {
    float4 acc = hs4[d * 32 + lane];
    int e = g_rs[d], end = g_rs[d + 1];
    for (; e + 8 <= end; e += 8) {
        int s0 = g_col[e],     s1 = g_col[e + 1], s2 = g_col[e + 2], s3 = g_col[e + 3];
        int s4 = g_col[e + 4], s5 = g_col[e + 5], s6 = g_col[e + 6], s7 = g_col[e + 7];
        float4 v0 = hs4[s0 * 32 + lane];
        float4 v1 = hs4[s1 * 32 + lane];
        float4 v2 = hs4[s2 * 32 + lane];
        float4 v3 = hs4[s3 * 32 + lane];
        float4 v4 = hs4[s4 * 32 + lane];
        float4 v5 = hs4[s5 * 32 + lane];
        float4 v6 = hs4[s6 * 32 + lane];
        float4 v7 = hs4[s7 * 32 + lane];
        acc.x += ((v0.x + v1.x) + (v2.x + v3.x)) + ((v4.x + v5.x) + (v6.x + v7.x));
        acc.y += ((v0.y + v1.y) + (v2.y + v3.y)) + ((v4.y + v5.y) + (v6.y + v7.y));
        acc.z += ((v0.z + v1.z) + (v2.z + v3.z)) + ((v4.z + v5.z) + (v6.z + v7.z));
        acc.w += ((v0.w + v1.w) + (v2.w + v3.w)) + ((v4.w + v5.w) + (v6.w + v7.w));
    }
    for (; e + 2 <= end; e += 2) {
        int s0 = g_col[e], s1 = g_col[e + 1];
        float4 v0 = hs4[s0 * 32 + lane];
        float4 v1 = hs4[s1 * 32 + lane];
        acc.x += v0.x + v1.x; acc.y += v0.y + v1.y;
        acc.z += v0.z + v1.z; acc.w += v0.w + v1.w;
    }
    if (e < end) {
        int s = g_col[e];
        float4 v = hs4[s * 32 + lane];
        acc.x += v.x; acc.y += v.y; acc.z += v.z; acc.w += v.w;
    }
    return acc;
}

// launch 6: layer-1 aggregation + relu.  One warp per dst node.
__global__ void k_agg_relu(const float* __restrict__ hs, const float* __restrict__ bias,
                           float* __restrict__ out) {
    int d = blockIdx.x * (blockDim.x >> 5) + (threadIdx.x >> 5);
    int lane = threadIdx.x & 31;
    if (d >= NN) return;
    float4 acc = agg_row((const float4*)hs, d, lane);
    float sc = g_dis[d];
    float4 bb = ((const float4*)bias)[lane];
    float4 o;
    o.x = fmaxf(fmaf(sc, acc.x, bb.x), 0.f);
    o.y = fmaxf(fmaf(sc, acc.y, bb.y), 0.f);
    o.z = fmaxf(fmaf(sc, acc.z, bb.z), 0.f);
    o.w = fmaxf(fmaf(sc, acc.w, bb.w), 0.f);
    ((float4*)out)[d * 32 + lane] = o;
}

// launch 8: layer-2 aggregation + relu + mean-pool scatter
__global__ void k_agg_pool(const float* __restrict__ hs, const float* __restrict__ bias) {
    int d = blockIdx.x * (blockDim.x >> 5) + (threadIdx.x >> 5);
    int lane = threadIdx.x & 31;
    if (d >= NN) return;
    float4 acc = agg_row((const float4*)hs, d, lane);
    float sc = g_dis[d];
    float4 bb = ((const float4*)bias)[lane];
    float4 o;
    o.x = fmaxf(fmaf(sc, acc.x, bb.x), 0.f);
    o.y = fmaxf(fmaf(sc, acc.y, bb.y), 0.f);
    o.z = fmaxf(fmaf(sc, acc.z, bb.z), 0.f);
    o.w = fmaxf(fmaf(sc, acc.w, bb.w), 0.f);
    int g = g_bat[d];
    float* p = g_pool + g * C + lane * 4;
    atomicAdd(p + 0, o.x);
    atomicAdd(p + 1, o.y);
    atomicAdd(p + 2, o.z);
    atomicAdd(p + 3, o.w);
}

// launch 9: 128 threads, one graph per thread. FC + log_softmax.
__global__ void k_fc(const float* __restrict__ Wfc, const float* __restrict__ bfc,
                     float* __restrict__ out) {
    __shared__ float Wf[C * OC];
    int t = threadIdx.x;
    for (int i = t; i < C * OC; i += 128) Wf[i] = Wfc[i];
    __syncthreads();

    float inv = 1.0f / fmaxf((float)g_gcnt[t], 1.0f);
    float acc[OC];
#pragma unroll
    for (int j = 0; j < OC; j++) acc[j] = bfc[j];
    for (int k = 0; k < C; k++) {
        float p = g_pool[t * C + k] * inv;
#pragma unroll
        for (int j = 0; j < OC; j++) acc[j] += p * Wf[k * OC + j];
    }
    float m = acc[0];
#pragma unroll
    for (int j = 1; j < OC; j++) m = fmaxf(m, acc[j]);
    float sum = 0.f;
#pragma unroll
    for (int j = 0; j < OC; j++) sum += expf(acc[j] - m);
    float lse = m + logf(sum);
#pragma unroll
    for (int j = 0; j < OC; j++) out[t * OC + j] = acc[j] - lse;
}

extern "C" void kernel_launch(void* const* d_in, const int* in_sizes, int n_in,
                              void* d_out, int out_size) {
    const float* x     = (const float*)d_in[0];
    const void*  ei    = d_in[1];
    const void*  batch = d_in[2];
    const float* W1    = (const float*)d_in[3];
    const float* b1    = (const float*)d_in[4];
    const float* W2    = (const float*)d_in[5];
    const float* b2    = (const float*)d_in[6];
    const float* Wfc   = (const float*)d_in[7];
    const float* bfc   = (const float*)d_in[8];
    float* out = (float*)d_out;

    float *A, *X2, *dis;
    cudaGetSymbolAddress((void**)&A,   g_A);
    cudaGetSymbolAddress((void**)&X2,  g_X2);
    cudaGetSymbolAddress((void**)&dis, g_dis);

    size_t smem = (size_t)(C * C + 64 * C) * sizeof(float);   // 96KB
    cudaFuncSetAttribute(k_gemm, cudaFuncAttributeMaxDynamicSharedMemorySize, (int)smem);

    int initg = (NG * C + 255) / 256;
    if (initg < NBLK) initg = NBLK;

    k_init<<<initg, 256>>>((const int*)ei);                   // 0
    k_convert_hist<<<(NE / 2 + 255) / 256, 256>>>(ei, batch); // 1
    k_scanA<<<NBLK, 256>>>();                                 // 2

    // Layer 1 (gemm only needs x, W1, dis)
    k_gemm<<<(NN + 63) / 64, 256, smem>>>(x, W1, dis, A);     // 3  <- ncu lands here
    k_scanB<<<NBLK, 256>>>();                                 // 4
    k_fill<<<(NE + 255) / 256, 256>>>();                      // 5
    k_agg_relu<<<(NN + 7) / 8, 256>>>(A, b1, X2);             // 6

    // Layer 2
    k_gemm<<<(NN + 63) / 64, 256, smem>>>(X2, W2, dis, A);    // 7
    k_agg_pool<<<(NN + 7) / 8, 256>>>(A, b2);                 // 8

    // Head
    k_fc<<<1, 128>>>(Wfc, bfc, out);                          // 9
}